// round 9
// baseline (speedup 1.0000x reference)
#include <cuda_runtime.h>

#define HH 512
#define WW 512
#define ROWF 1536
#define NB 4
#define ITERS 30
#define NELEM (NB * HH * WW * 3)

__device__ float  g_buf0[NELEM];
__device__ float  g_buf1[NELEM];
__device__ double g_sums[ITERS];

__device__ __forceinline__ int refl(int i, int n) {
    // np "reflect": -1 -> 1, n -> n-2
    if (i < 0) i = -i;
    if (i >= n) i = 2 * n - 2 - i;
    return i;
}

__global__ void zero_sums_kernel() {
    if (threadIdx.x < ITERS) g_sums[threadIdx.x] = 0.0;
}

// Tile 32 wide x 64 tall; block (32,8); warp ty owns output rows [8ty, 8ty+8).
// 512 blocks; 5 blocks/SM x 148 = 740 >= 512 -> one wave.
// Single post-load barrier; warps independent afterwards. Channel loop is INNER
// (unrolled) so each step has 3 independent div/shfl chains (ILP x3).
// Halo rb (x=-1,32) precomputed data-parallel in lanes 0..29 ((row,ch) pairs).
__global__ __launch_bounds__(256, 5) void rl_iter_kernel(
    const float* __restrict__ latent_in,
    const float* __restrict__ inputs,
    const float* __restrict__ k1g,
    const float* __restrict__ k2g,
    float* __restrict__ latent_out,
    int iter)
{
    __shared__ float  s_lat[68][108];
    __shared__ double s_red[8];
    __shared__ int    s_done;

    const int tx  = threadIdx.x;
    const int ty  = threadIdx.y;
    const int tid = ty * 32 + tx;
    const int n   = blockIdx.z;
    const int r0  = blockIdx.y * 64;
    const int c0  = blockIdx.x * 32;

    if (tid == 0) {
        int done = 0;
        for (int j = 0; j < iter; j++) {
            double d = fabs(1.0 - g_sums[j] * (1.0 / (double)NELEM));
            if (d < 1e-5) done = 1;
        }
        s_done = done;
    }
    __syncthreads();

    const int img_off = n * (HH * ROWF);
    const float* lat_img = latent_in  + img_off;
    float*       out_img = latent_out + img_off;

    if (s_done) {   // frozen: propagate latent through the ping-pong chain
        for (int y = ty; y < 64; y += 8) {
            int base = (r0 + y) * ROWF + c0 * 3;
            for (int f = tx; f < 96; f += 32)
                out_img[base + f] = lat_img[base + f];
        }
        return;
    }

    // separable factors: k = u * v^T, v = middle row, u = middle col / center.
    const float v0 = k1g[9],  v1 = k1g[12], v2 = k1g[15];
    const float u0 = __fdividef(k1g[3],  k1g[12]);
    const float u2 = __fdividef(k1g[21], k1g[12]);
    const float w0 = k2g[9],  w1 = k2g[12], w2 = k2g[15];
    const float t0 = __fdividef(k2g[3],  k2g[12]);
    const float t2 = __fdividef(k2g[21], k2g[12]);

    const float* in_img = inputs + img_off;

    // ---- phase A: cooperative load of latent tile (68 x 108, reflect halo 2) ----
    {
        const bool xin2 = (c0 >= 2) && (c0 <= WW - 34);
        for (int r = ty; r < 68; r += 8) {
            int gr = refl(r0 - 2 + r, HH);
            const float* rp = lat_img + gr * ROWF;
            if (xin2) {
                const float* p = rp + (c0 - 2) * 3;
                s_lat[r][tx]      = p[tx];
                s_lat[r][tx + 32] = p[tx + 32];
                s_lat[r][tx + 64] = p[tx + 64];
                if (tx < 12) s_lat[r][tx + 96] = p[tx + 96];
            } else {
                for (int f = tx; f < 108; f += 32) {
                    int col = f / 3, ch = f - 3 * col;
                    int gc = refl(c0 - 2 + col, WW);
                    s_lat[r][f] = rp[gc * 3 + ch];
                }
            }
        }
    }
    __syncthreads();

    const int w8 = ty * 8;

    // ---- halo rb precompute: lane j<30 owns (row=j/3 in [0,10), ch=j%3) ----
    float rbL, rbR;
    {
        int j   = (tx < 30) ? tx : (tx - 30);   // lanes 30,31 duplicate harmlessly
        int row = j / 3;
        int ch  = j - 3 * row;
        int yb  = w8 + row;                      // s_lat rows yb..yb+2 feed this rb row
        // left halo pixel (global x = c0-1): s_lat pixel cols 0..2 (bases 0,3,6)
        float hA = fmaf(v0, s_lat[yb][ch],     fmaf(v1, s_lat[yb][3 + ch],     v2 * s_lat[yb][6 + ch]));
        float hB = fmaf(v0, s_lat[yb + 1][ch], fmaf(v1, s_lat[yb + 1][3 + ch], v2 * s_lat[yb + 1][6 + ch]));
        float hC = fmaf(v0, s_lat[yb + 2][ch], fmaf(v1, s_lat[yb + 2][3 + ch], v2 * s_lat[yb + 2][6 + ch]));
        float estL = fmaf(u0, hA, fmaf(u2, hC, hB));
        // right halo pixel (global x = c0+32): s_lat pixel cols 33..35 (bases 99,102,105)
        float gA = fmaf(v0, s_lat[yb][99 + ch],     fmaf(v1, s_lat[yb][102 + ch],     v2 * s_lat[yb][105 + ch]));
        float gB = fmaf(v0, s_lat[yb + 1][99 + ch], fmaf(v1, s_lat[yb + 1][102 + ch], v2 * s_lat[yb + 1][105 + ch]));
        float gC = fmaf(v0, s_lat[yb + 2][99 + ch], fmaf(v1, s_lat[yb + 2][102 + ch], v2 * s_lat[yb + 2][105 + ch]));
        float estR = fmaf(u0, gA, fmaf(u2, gC, gB));
        int gy  = refl(r0 + w8 - 1 + row, HH);
        int gxL = refl(c0 - 1, WW);
        int gxR = refl(c0 + 32, WW);
        const float* inrow = in_img + gy * ROWF;
        rbL = __fdividef(inrow[gxL * 3 + ch], estL);
        rbR = __fdividef(inrow[gxR * 3 + ch], estR);
    }

    // ---- warp-autonomous fused stages: s outer, ch inner (unrolled, ILP x3) ----
    const int xm = 3 * tx + 6;
    float fsum = 0.f;
    float hl0[3], hl1[3], hr0[3], hr1[3];

    {   // prologue: h_lat rows w8-2, w8-1 -> s_lat rows w8, w8+1
        const float* r = s_lat[w8];
        const float* q = s_lat[w8 + 1];
        #pragma unroll
        for (int ch = 0; ch < 3; ch++) {
            hl0[ch] = fmaf(v0, r[xm - 3 + ch], fmaf(v1, r[xm + ch], v2 * r[xm + 3 + ch]));
            hl1[ch] = fmaf(v0, q[xm - 3 + ch], fmaf(v1, q[xm + ch], v2 * q[xm + 3 + ch]));
            hr0[ch] = 0.f; hr1[ch] = 0.f;
        }
    }

    #pragma unroll
    for (int s = 0; s < 10; s++) {
        const int y_rb = w8 - 1 + s;             // tile-local rb row
        const float* r = s_lat[y_rb + 3];        // lat row y_rb+1
        const int gy = refl(r0 + y_rb, HH);
        const float* inrow = in_img + gy * ROWF + (c0 + tx) * 3;
        float* outp = (s >= 2) ? (out_img + (r0 + y_rb - 1) * ROWF + (c0 + tx) * 3) : 0;
        #pragma unroll
        for (int ch = 0; ch < 3; ch++) {
            float hl2 = fmaf(v0, r[xm - 3 + ch], fmaf(v1, r[xm + ch], v2 * r[xm + 3 + ch]));
            float est = fmaf(u0, hl0[ch], fmaf(u2, hl2, hl1[ch]));
            float rb  = __fdividef(inrow[ch], est);
            float lf = __shfl_up_sync(0xffffffffu, rb, 1);
            float rt = __shfl_down_sync(0xffffffffu, rb, 1);
            float hL = __shfl_sync(0xffffffffu, rbL, s * 3 + ch);
            float hR = __shfl_sync(0xffffffffu, rbR, s * 3 + ch);
            if (tx == 0)  lf = hL;
            if (tx == 31) rt = hR;
            float hr2 = fmaf(w0, lf, fmaf(w1, rb, w2 * rt));
            if (s >= 2) {                        // output row yo = y_rb - 1
                float e = fmaf(t0, hr0[ch], fmaf(t2, hr2, hr1[ch]));
                fsum += e;
                float latc = s_lat[y_rb + 1][xm + ch];
                outp[ch] = latc * e;
            }
            hl0[ch] = hl1[ch]; hl1[ch] = hl2;
            hr0[ch] = hr1[ch]; hr1[ch] = hr2;
        }
    }

    // ---- block reduction -> one double atomic ----
    #pragma unroll
    for (int off = 16; off > 0; off >>= 1)
        fsum += __shfl_down_sync(0xffffffffu, fsum, off);
    if (tx == 0) s_red[ty] = (double)fsum;
    __syncthreads();
    if (tid == 0) {
        double v = 0.0;
        #pragma unroll
        for (int i = 0; i < 8; i++) v += s_red[i];
        atomicAdd(&g_sums[iter], v);
    }
}

extern "C" void kernel_launch(void* const* d_in, const int* in_sizes, int n_in,
                              void* d_out, int out_size) {
    const float* inputs = (const float*)d_in[0];
    const float* k1     = (const float*)d_in[1];
    const float* k2     = (const float*)d_in[2];
    float* out = (float*)d_out;

    float *b0 = nullptr, *b1 = nullptr;
    cudaGetSymbolAddress((void**)&b0, g_buf0);
    cudaGetSymbolAddress((void**)&b1, g_buf1);

    zero_sums_kernel<<<1, 32>>>();

    dim3 blk(32, 8, 1);
    dim3 grid(16, 8, NB);   // 512 blocks, one wave at >=4 blocks/SM
    const float* cur = inputs;
    for (int it = 0; it < ITERS; it++) {
        float* nxt = (it == ITERS - 1) ? out : ((it & 1) ? b1 : b0);
        rl_iter_kernel<<<grid, blk>>>(cur, inputs, k1, k2, nxt, it);
        cur = nxt;
    }
}